// round 14
// baseline (speedup 1.0000x reference)
#include <cuda_runtime.h>
#include <cuda_bf16.h>
#include <math.h>
#include <stdint.h>

#define DEPTH  8
#define DDIM   1024
#define DI     2048
#define NSTATE 16
#define DCONV  4
#define DTRANK 64
#define BB     2
#define LLEN   2048
#define ROWS   (BB*LLEN)           // 4096
#define XZW    (2*DI)              // 4096
#define XDBLW  (DTRANK + 2*NSTATE) // 96

// ---------------- scratch (static device globals; no allocation) ----------
__device__ float g_xz  [(size_t)ROWS * XZW];
__device__ float g_xs  [(size_t)ROWS * DI];
__device__ float g_xdbl[(size_t)ROWS * XDBLW];
__device__ float g_delta[(size_t)ROWS * DI];
__device__ float g_y   [(size_t)ROWS * DI];
__device__ float g_x   [(size_t)ROWS * DDIM];
__device__ float g_sa  [(size_t)ROWS * 4 * DI];   // A split [R, 4K] = [h|l|h|l]
__device__ float g_sw  [(size_t)XZW * 4 * DDIM];  // B split [N, 4K] = [h|h|l|l]
__device__ float g_sdt [(size_t)ROWS * 4 * DTRANK];

// ======================= helpers ==========================================
__device__ __forceinline__ uint32_t s2u(const void* p) {
    uint32_t a;
    asm("{ .reg .u64 t; cvta.to.shared.u64 t, %1; cvt.u32.u64 %0, t; }"
        : "=r"(a) : "l"(p));
    return a;
}
#define CP16(dst, src) \
    asm volatile("cp.async.cg.shared.global [%0], [%1], 16;" :: "r"(dst), "l"(src))
#define CP_COMMIT()  asm volatile("cp.async.commit_group;" ::: "memory")
#define CP_WAIT1()   asm volatile("cp.async.wait_group 1;" ::: "memory")
#define CP_WAIT0()   asm volatile("cp.async.wait_group 0;" ::: "memory")

__device__ __forceinline__ void mma_tf32(float* c, uint32_t a0, uint32_t a1,
                                         uint32_t a2, uint32_t a3,
                                         uint32_t b0, uint32_t b1) {
    asm volatile(
        "mma.sync.aligned.m16n8k8.row.col.f32.tf32.tf32.f32 "
        "{%0,%1,%2,%3}, {%4,%5,%6,%7}, {%8,%9}, {%0,%1,%2,%3};"
        : "+f"(c[0]), "+f"(c[1]), "+f"(c[2]), "+f"(c[3])
        : "r"(a0), "r"(a1), "r"(a2), "r"(a3), "r"(b0), "r"(b1));
}
// Round-to-nearest mask to tf32 precision (10 explicit mantissa bits).
// Pure integer ops; cannot be elided by the compiler.
__device__ __forceinline__ float tf32_rn(float x) {
    uint32_t u = __float_as_uint(x);
    u = (u + 0xFFFu + ((u >> 13) & 1u)) & 0xFFFFE000u;
    return __uint_as_float(u);
}

// ======================= precision splits (4-segment) =====================
// A-side: out[r, 0:K)=h, [K:2K)=l, [2K:3K)=h, [3K:4K)=l.
__global__ __launch_bounds__(256) void split_a_kernel(
    const float* __restrict__ X, int R, int K, int ldx, float* __restrict__ out)
{
    long i = (long)blockIdx.x * blockDim.x + threadIdx.x;
    if (i >= (long)R * K) return;
    int k = (int)(i % K);
    long r = i / K;
    float x = X[r * (long)ldx + k];
    float h = tf32_rn(x);
    float l = tf32_rn(x - h);
    float* o = out + r * (long)(4 * K);
    o[k] = h; o[K + k] = l; o[2 * K + k] = h; o[3 * K + k] = l;
}
// B-side: out[r, 0:K)=h, [K:2K)=h, [2K:3K)=l, [3K:4K)=l; rows >= R zeroed.
__global__ __launch_bounds__(256) void split_b_kernel(
    const float* __restrict__ X, int R, int Rpad, int K, float* __restrict__ out)
{
    long i = (long)blockIdx.x * blockDim.x + threadIdx.x;
    if (i >= (long)Rpad * K) return;
    int k = (int)(i % K);
    long r = i / K;
    float x = (r < R) ? X[r * (long)K + k] : 0.f;
    float h = tf32_rn(x);
    float l = tf32_rn(x - h);
    float* o = out + r * (long)(4 * K);
    o[k] = h; o[K + k] = h; o[2 * K + k] = l; o[3 * K + k] = l;
}

// ======================= 4xTF32 GEMM with short-chain spill ===============
// C[M,N] = A'[M,K4] * W'[N,K4]^T, K4 = 4K; segments sum hh + lh + hl + ll.
// KEY: the legacy-mma fp32 accumulator on sm_103 is suspected to carry
// reduced precision (~2^-13 relative) per chained step. Keep each mma chain
// only 2 steps long (one BK=16 chunk) and spill into persistent CUDA-core
// fp32 registers, which accumulate exactly.
#define BKC   16
#define SSTR  20   // padded smem row stride (floats): conflict-free

__global__ __launch_bounds__(256) void tf32_gemm_kernel(
    const float* __restrict__ A,
    const float* __restrict__ W,
    float* __restrict__ C, int ldc,
    int Ntrue, int K4,
    int do_sp, const float* __restrict__ bias)
{
    __shared__ float sA[2][128 * SSTR];
    __shared__ float sB[2][128 * SSTR];

    const int tid = threadIdx.x;
    const int m0 = blockIdx.y * 128;
    const int n0 = blockIdx.x * 128;

    // ---- global->smem: each thread loads 2x16B of one 64B chunk row ------
    const int ldrow = tid >> 1;           // 0..127
    const int ldoff = (tid & 1) * 32;     // 0 or 32 bytes
    const char* gA = (const char*)(A + (size_t)(m0 + ldrow) * K4) + ldoff;
    const char* gB = (const char*)(W + (size_t)(n0 + ldrow) * K4) + ldoff;
    const uint32_t dA[2] = { s2u(&sA[0][0]) + ldrow * (SSTR * 4) + ldoff,
                             s2u(&sA[1][0]) + ldrow * (SSTR * 4) + ldoff };
    const uint32_t dB[2] = { s2u(&sB[0][0]) + ldrow * (SSTR * 4) + ldoff,
                             s2u(&sB[1][0]) + ldrow * (SSTR * 4) + ldoff };

    auto load_chunk = [&](int kc, int buf) {
        const char* pa = gA + (size_t)kc * (BKC * 4);
        const char* pb = gB + (size_t)kc * (BKC * 4);
        CP16(dA[buf],      pa);
        CP16(dA[buf] + 16, pa + 16);
        CP16(dB[buf],      pb);
        CP16(dB[buf] + 16, pb + 16);
    };

    // ---- warp/lane decomposition ----------------------------------------
    const int wid = tid >> 5, lane = tid & 31;
    const int wm = wid & 1;        // 0..1  (64 rows each)
    const int wn = wid >> 1;       // 0..3  (32 cols each)
    const int g = lane >> 2, t = lane & 3;

    float accP[4][4][4];   // persistent fp32 accumulation (exact)
    float acc[4][4][4];    // short mma chain (spilled every chunk)
#pragma unroll
    for (int i = 0; i < 4; i++)
#pragma unroll
        for (int j = 0; j < 4; j++)
#pragma unroll
            for (int q = 0; q < 4; q++) { accP[i][j][q] = 0.f; acc[i][j][q] = 0.f; }

    const int nk = K4 / BKC;
    load_chunk(0, 0);
    CP_COMMIT();

    for (int k = 0; k < nk; k++) {
        const int buf = k & 1;
        if (k + 1 < nk) {
            load_chunk(k + 1, buf ^ 1);
            CP_COMMIT();
            CP_WAIT1();
        } else {
            CP_WAIT0();
        }
        __syncthreads();

        const float* pA = &sA[buf][0];
        const float* pB = &sB[buf][0];
#pragma unroll
        for (int ks = 0; ks < 2; ks++) {
            const int kb = ks * 8 + t;
            uint32_t af[4][4], bf[4][2];
#pragma unroll
            for (int mt = 0; mt < 4; mt++) {
                const int r = wm * 64 + mt * 16 + g;
                af[mt][0] = *(const uint32_t*)&pA[r * SSTR + kb];
                af[mt][1] = *(const uint32_t*)&pA[(r + 8) * SSTR + kb];
                af[mt][2] = *(const uint32_t*)&pA[r * SSTR + kb + 4];
                af[mt][3] = *(const uint32_t*)&pA[(r + 8) * SSTR + kb + 4];
            }
#pragma unroll
            for (int nt = 0; nt < 4; nt++) {
                const int cc = wn * 32 + nt * 8 + g;
                bf[nt][0] = *(const uint32_t*)&pB[cc * SSTR + kb];
                bf[nt][1] = *(const uint32_t*)&pB[cc * SSTR + kb + 4];
            }
#pragma unroll
            for (int mt = 0; mt < 4; mt++)
#pragma unroll
                for (int nt = 0; nt < 4; nt++)
                    mma_tf32(acc[mt][nt], af[mt][0], af[mt][1], af[mt][2],
                             af[mt][3], bf[nt][0], bf[nt][1]);
        }
        // ---- spill the 2-step mma chain into exact fp32 accumulators -----
#pragma unroll
        for (int mt = 0; mt < 4; mt++)
#pragma unroll
            for (int nt = 0; nt < 4; nt++)
#pragma unroll
                for (int q = 0; q < 4; q++) {
                    accP[mt][nt][q] += acc[mt][nt][q];
                    acc[mt][nt][q] = 0.f;
                }
        __syncthreads();
    }

    // ---- epilogue --------------------------------------------------------
#pragma unroll
    for (int mt = 0; mt < 4; mt++) {
        const int r0 = m0 + wm * 64 + mt * 16 + g;
#pragma unroll
        for (int nt = 0; nt < 4; nt++) {
            const int cc = n0 + wn * 32 + nt * 8 + t * 2;
            if (cc >= Ntrue) continue;
            float v0 = accP[mt][nt][0], v1 = accP[mt][nt][1];
            float v2 = accP[mt][nt][2], v3 = accP[mt][nt][3];
            if (do_sp) {
                const float b0 = bias[cc], b1 = bias[cc + 1];
                v0 += b0; v1 += b1; v2 += b0; v3 += b1;
                v0 = fmaxf(v0, 0.f) + log1pf(expf(-fabsf(v0)));
                v1 = fmaxf(v1, 0.f) + log1pf(expf(-fabsf(v1)));
                v2 = fmaxf(v2, 0.f) + log1pf(expf(-fabsf(v2)));
                v3 = fmaxf(v3, 0.f) + log1pf(expf(-fabsf(v3)));
            }
            *(float2*)(C + (size_t)r0 * ldc + cc)       = make_float2(v0, v1);
            *(float2*)(C + (size_t)(r0 + 8) * ldc + cc) = make_float2(v2, v3);
        }
    }
}

// ---------------- depthwise causal conv (width 4) + bias + silu -----------
__global__ __launch_bounds__(256) void conv_silu_kernel(
    const float* __restrict__ xz, const float* __restrict__ cw,
    const float* __restrict__ cb, float* __restrict__ xs)
{
    const int i = blockIdx.x * blockDim.x + threadIdx.x;
    if (i >= ROWS * DI) return;
    const int d = i & (DI - 1);
    const int r = i >> 11;
    const int t = r & (LLEN - 1);
    float acc = cb[d];
    const float* base = xz + (size_t)r * XZW + d;
#pragma unroll
    for (int j = 0; j < DCONV; j++) {
        const int tt = t - (DCONV - 1) + j;
        if (tt >= 0)
            acc += cw[d * DCONV + j] * base[(long)(tt - t) * XZW];
    }
    xs[i] = acc / (1.f + __expf(-acc));
}

// ---------------- selective scan: 16 lanes per (b,d) channel --------------
__global__ __launch_bounds__(128) void scan_kernel(
    const float* __restrict__ xs, const float* __restrict__ delta,
    const float* __restrict__ xdbl, const float* __restrict__ A_log,
    const float* __restrict__ Dp, float* __restrict__ y)
{
    const int lane = threadIdx.x & 15;
    const int ch = blockIdx.x * (blockDim.x >> 4) + (threadIdx.x >> 4);
    const int b = ch / DI, d = ch & (DI - 1);
    const float A  = -expf(A_log[d * NSTATE + lane]);
    const float Dd = Dp[d];

    const float* xsP = xs    + (size_t)b * LLEN * DI + d;
    const float* dlP = delta + (size_t)b * LLEN * DI + d;
    const float* bcP = xdbl  + (size_t)b * LLEN * XDBLW + DTRANK + lane;
    float*       yP  = y     + (size_t)b * LLEN * DI + d;

    float h = 0.f;
    for (int t = 0; t < LLEN; t++) {
        const float dt = dlP[0];
        const float xt = xsP[0];
        const float Bt = bcP[0];
        const float Ct = bcP[NSTATE];
        const float dA = __expf(dt * A);
        h = dA * h + (dt * xt) * Bt;
        float p = h * Ct;
        p += __shfl_xor_sync(0xffffffffu, p, 1);
        p += __shfl_xor_sync(0xffffffffu, p, 2);
        p += __shfl_xor_sync(0xffffffffu, p, 4);
        p += __shfl_xor_sync(0xffffffffu, p, 8);
        if (lane == 0) yP[0] = p + Dd * xt;
        xsP += DI; dlP += DI; bcP += XDBLW; yP += DI;
    }
}

// ---------------- gate: y *= silu(z) --------------------------------------
__global__ __launch_bounds__(256) void gate_kernel(
    float* __restrict__ y, const float* __restrict__ xz)
{
    const int i = blockIdx.x * blockDim.x + threadIdx.x;
    if (i >= ROWS * DI) return;
    const int d = i & (DI - 1);
    const int r = i >> 11;
    const float z = xz[(size_t)r * XZW + DI + d];
    y[i] *= z / (1.f + __expf(-z));
}

// ---------------- rmsnorm per row -----------------------------------------
__global__ __launch_bounds__(256) void rmsnorm_kernel(
    const float* __restrict__ in, const float* __restrict__ w,
    float* __restrict__ out)
{
    const int r = blockIdx.x;
    const int tid = threadIdx.x;
    const float* row = in + (size_t)r * DDIM;
    float v[4];
    float ss = 0.f;
#pragma unroll
    for (int j = 0; j < 4; j++) {
        v[j] = row[tid + j * 256];
        ss += v[j] * v[j];
    }
#pragma unroll
    for (int o = 16; o > 0; o >>= 1) ss += __shfl_xor_sync(0xffffffffu, ss, o);
    __shared__ float ws[8];
    if ((tid & 31) == 0) ws[tid >> 5] = ss;
    __syncthreads();
    float tot = 0.f;
#pragma unroll
    for (int k = 0; k < 8; k++) tot += ws[k];
    const float inv = rsqrtf(tot * (1.f / (float)DDIM) + 1e-5f);
#pragma unroll
    for (int j = 0; j < 4; j++)
        out[(size_t)r * DDIM + tid + j * 256] = v[j] * inv * w[tid + j * 256];
}

// ---------------- host launch ---------------------------------------------
static inline int cdiv(long a, int b) { return (int)((a + b - 1) / b); }

extern "C" void kernel_launch(void* const* d_in, const int* in_sizes, int n_in,
                              void* d_out, int out_size)
{
    const float* x0   = (const float*)d_in[0];
    const float* Wi   = (const float*)d_in[1];   // [8, 4096, 1024]
    const float* cw   = (const float*)d_in[2];   // [8, 2048, 4]
    const float* cb   = (const float*)d_in[3];   // [8, 2048]
    const float* Wx   = (const float*)d_in[4];   // [8, 96, 2048]
    const float* Wdt  = (const float*)d_in[5];   // [8, 2048, 64]
    const float* bdt  = (const float*)d_in[6];   // [8, 2048]
    const float* Alog = (const float*)d_in[7];   // [8, 2048, 16]
    const float* Dp   = (const float*)d_in[8];   // [8, 2048]
    const float* Wo   = (const float*)d_in[9];   // [8, 1024, 2048]
    const float* rw   = (const float*)d_in[10];  // [8, 1024]

    float *xz, *xs, *xdbl, *delta, *y, *xb, *sa, *sw, *sdt;
    cudaGetSymbolAddress((void**)&xz,    g_xz);
    cudaGetSymbolAddress((void**)&xs,    g_xs);
    cudaGetSymbolAddress((void**)&xdbl,  g_xdbl);
    cudaGetSymbolAddress((void**)&delta, g_delta);
    cudaGetSymbolAddress((void**)&y,     g_y);
    cudaGetSymbolAddress((void**)&xb,    g_x);
    cudaGetSymbolAddress((void**)&sa,    g_sa);
    cudaGetSymbolAddress((void**)&sw,    g_sw);
    cudaGetSymbolAddress((void**)&sdt,   g_sdt);

    const float* xin = x0;
    for (int l = 0; l < DEPTH; l++) {
        // ---- in_proj: [4096,1024] x [4096,1024]^T -> xz [4096,4096] ------
        split_a_kernel<<<cdiv((long)ROWS * DDIM, 256), 256>>>(
            xin, ROWS, DDIM, DDIM, sa);
        split_b_kernel<<<cdiv((long)XZW * DDIM, 256), 256>>>(
            Wi + (size_t)l * XZW * DDIM, XZW, XZW, DDIM, sw);
        tf32_gemm_kernel<<<dim3(XZW / 128, ROWS / 128), 256>>>(
            sa, sw, xz, XZW, XZW, 4 * DDIM, 0, nullptr);

        // ---- depthwise causal conv + silu -> xs [4096,2048] --------------
        conv_silu_kernel<<<(ROWS * DI) / 256, 256>>>(
            xz, cw + (size_t)l * DI * DCONV, cb + (size_t)l * DI, xs);

        // ---- x_proj: [4096,2048] x [96,2048]^T -> xdbl [4096,96] ---------
        split_a_kernel<<<cdiv((long)ROWS * DI, 256), 256>>>(
            xs, ROWS, DI, DI, sa);
        split_b_kernel<<<cdiv((long)128 * DI, 256), 256>>>(
            Wx + (size_t)l * XDBLW * DI, XDBLW, 128, DI, sw);
        tf32_gemm_kernel<<<dim3(1, ROWS / 128), 256>>>(
            sa, sw, xdbl, XDBLW, XDBLW, 4 * DI, 0, nullptr);

        // ---- dt_proj + softplus: [4096,64] x [2048,64]^T -> delta --------
        split_a_kernel<<<cdiv((long)ROWS * DTRANK, 256), 256>>>(
            xdbl, ROWS, DTRANK, XDBLW, sdt);
        split_b_kernel<<<cdiv((long)DI * DTRANK, 256), 256>>>(
            Wdt + (size_t)l * DI * DTRANK, DI, DI, DTRANK, sw);
        tf32_gemm_kernel<<<dim3(DI / 128, ROWS / 128), 256>>>(
            sdt, sw, delta, DI, DI, 4 * DTRANK, 1, bdt + (size_t)l * DI);

        // ---- selective scan (+ D skip) -----------------------------------
        scan_kernel<<<(BB * DI) / 8, 128>>>(
            xs, delta, xdbl, Alog + (size_t)l * DI * NSTATE, Dp + (size_t)l * DI, y);

        // ---- gate --------------------------------------------------------
        gate_kernel<<<(ROWS * DI) / 256, 256>>>(y, xz);

        // ---- out_proj: [4096,2048] x [1024,2048]^T -> xz [4096,1024] -----
        split_a_kernel<<<cdiv((long)ROWS * DI, 256), 256>>>(
            y, ROWS, DI, DI, sa);
        split_b_kernel<<<cdiv((long)DDIM * DI, 256), 256>>>(
            Wo + (size_t)l * DDIM * DI, DDIM, DDIM, DI, sw);
        tf32_gemm_kernel<<<dim3(DDIM / 128, ROWS / 128), 256>>>(
            sa, sw, xz, DDIM, DDIM, 4 * DI, 0, nullptr);

        // ---- rmsnorm -----------------------------------------------------
        float* outp = (l == DEPTH - 1) ? (float*)d_out : xb;
        rmsnorm_kernel<<<ROWS, 256>>>(xz, rw + (size_t)l * DDIM, outp);
        xin = xb;
    }
}

// round 15
// speedup vs baseline: 1.9127x; 1.9127x over previous
#include <cuda_runtime.h>
#include <cuda_bf16.h>
#include <math.h>
#include <stdint.h>

#define DEPTH  8
#define DDIM   1024
#define DI     2048
#define NSTATE 16
#define DCONV  4
#define DTRANK 64
#define BB     2
#define LLEN   2048
#define ROWS   (BB*LLEN)           // 4096
#define XZW    (2*DI)              // 4096
#define XDBLW  (DTRANK + 2*NSTATE) // 96

// ---------------- scratch (static device globals; no allocation) ----------
__device__ float g_xz  [(size_t)ROWS * XZW];
__device__ float g_xs  [(size_t)ROWS * DI];
__device__ float g_xdbl[(size_t)ROWS * XDBLW];
__device__ float g_delta[(size_t)ROWS * DI];
__device__ float g_y   [(size_t)ROWS * DI];
__device__ float g_x   [(size_t)ROWS * DDIM];
__device__ __nv_bfloat16 g_sa [(size_t)ROWS * 2 * DI];   // A split [R, 2K] = [h|l]
__device__ __nv_bfloat16 g_sw [(size_t)XZW * 2 * DDIM];  // B split [N, 2K] = [h|l]
__device__ __nv_bfloat16 g_sdt[(size_t)ROWS * 2 * DTRANK];

// ======================= helpers ==========================================
__device__ __forceinline__ uint32_t s2u(const void* p) {
    uint32_t a;
    asm("{ .reg .u64 t; cvta.to.shared.u64 t, %1; cvt.u32.u64 %0, t; }"
        : "=r"(a) : "l"(p));
    return a;
}
#define CP16(dst, src) \
    asm volatile("cp.async.cg.shared.global [%0], [%1], 16;" :: "r"(dst), "l"(src))
#define CP_COMMIT()  asm volatile("cp.async.commit_group;" ::: "memory")
#define CP_WAIT0()   asm volatile("cp.async.wait_group 0;" ::: "memory")

__device__ __forceinline__ void mma16816(float* c, uint32_t a0, uint32_t a1,
                                         uint32_t a2, uint32_t a3,
                                         uint32_t b0, uint32_t b1) {
    asm volatile(
        "mma.sync.aligned.m16n8k16.row.col.f32.bf16.bf16.f32 "
        "{%0,%1,%2,%3}, {%4,%5,%6,%7}, {%8,%9}, {%0,%1,%2,%3};"
        : "+f"(c[0]), "+f"(c[1]), "+f"(c[2]), "+f"(c[3])
        : "r"(a0), "r"(a1), "r"(a2), "r"(a3), "r"(b0), "r"(b1));
}

// ======================= compact bf16 2-way split =========================
// out[r, 0:K)=h, [K:2K)=l where x = h + l + O(2^-18 x); rows >= R zeroed.
__global__ __launch_bounds__(256) void split2_kernel(
    const float* __restrict__ X, int R, int Rpad, int K, int ldx,
    __nv_bfloat16* __restrict__ out)
{
    long i = (long)blockIdx.x * blockDim.x + threadIdx.x;
    if (i >= (long)Rpad * K) return;
    int k = (int)(i % K);
    long r = i / K;
    float x = (r < R) ? X[r * (long)ldx + k] : 0.f;
    __nv_bfloat16 h = __float2bfloat16(x);
    __nv_bfloat16 l = __float2bfloat16(x - __bfloat162float(h));
    __nv_bfloat16* o = out + r * (long)(2 * K);
    o[k] = h; o[K + k] = l;
}

// ======================= bf16 GEMM, 3 segments, chunk-spill ===============
// C[M,N] = sum over segment pairs {hh, lh, hl} of A_seg[M,K] * W_seg[N,K]^T.
// A,W layout: [rows, 2K] = [h|l].  128x128 CTA tile, BK=32, 256 threads,
// warp grid 2(M)x4(N), m16n8k16.  Each chunk's 2-step mma chain is spilled
// into exact CUDA-core fp32 accumulators (defeats the legacy-mma reduced-
// precision accumulator; proven in R14).  One __syncthreads per chunk.
#define BKC   32
#define SSTR  40   // padded smem row stride (bf16): conflict-free
#define SEGA_PACK 0x010u   // nibbles p0..p2: A segments 0,1,0
#define SEGB_PACK 0x100u   // nibbles p0..p2: B segments 0,0,1

__global__ __launch_bounds__(256) void bf16_gemm_kernel(
    const __nv_bfloat16* __restrict__ A,
    const __nv_bfloat16* __restrict__ W,
    float* __restrict__ C, int ldc,
    int Ntrue, int K,
    int do_sp, const float* __restrict__ bias)
{
    __shared__ __nv_bfloat16 sA[2][128 * SSTR];
    __shared__ __nv_bfloat16 sB[2][128 * SSTR];

    const int tid = threadIdx.x;
    const int m0 = blockIdx.y * 128;
    const int n0 = blockIdx.x * 128;

    // ---- global->smem: 2 threads per 64B chunk row, 2x16B each ----------
    const int ldrow = tid >> 1;           // 0..127
    const int ldoff = (tid & 1) * 32;     // 0 or 32 bytes
    const char* gA = (const char*)(A + (size_t)(m0 + ldrow) * (2 * K)) + ldoff;
    const char* gB = (const char*)(W + (size_t)(n0 + ldrow) * (2 * K)) + ldoff;
    const uint32_t dA[2] = { s2u(&sA[0][0]) + ldrow * (SSTR * 2) + ldoff,
                             s2u(&sA[1][0]) + ldrow * (SSTR * 2) + ldoff };
    const uint32_t dB[2] = { s2u(&sB[0][0]) + ldrow * (SSTR * 2) + ldoff,
                             s2u(&sB[1][0]) + ldrow * (SSTR * 2) + ldoff };

    const int nkr = K / BKC;              // chunks per segment
    const int total = 3 * nkr;

    auto load_chunk = [&](int c, int buf) {
        const int p = c / nkr;
        const int kk = c - p * nkr;
        const int sa_off = (int)((SEGA_PACK >> (4 * p)) & 3) * K + kk * BKC;
        const int sb_off = (int)((SEGB_PACK >> (4 * p)) & 3) * K + kk * BKC;
        const char* pa = gA + (size_t)sa_off * 2;
        const char* pb = gB + (size_t)sb_off * 2;
        CP16(dA[buf],      pa);
        CP16(dA[buf] + 16, pa + 16);
        CP16(dB[buf],      pb);
        CP16(dB[buf] + 16, pb + 16);
    };

    // ---- warp/lane decomposition ----------------------------------------
    const int wid = tid >> 5, lane = tid & 31;
    const int wm = wid & 1;        // 0..1  (64 rows each)
    const int wn = wid >> 1;       // 0..3  (32 cols each)
    const int g = lane >> 2, t = lane & 3;

    float accP[4][4][4];   // persistent fp32 accumulation (exact)
    float acc[4][4][4];    // 2-step mma chain, spilled every chunk
#pragma unroll
    for (int i = 0; i < 4; i++)
#pragma unroll
        for (int j = 0; j < 4; j++)
#pragma unroll
            for (int q = 0; q < 4; q++) { accP[i][j][q] = 0.f; acc[i][j][q] = 0.f; }

    load_chunk(0, 0);
    CP_COMMIT();

    for (int c = 0; c < total; c++) {
        const int buf = c & 1;
        CP_WAIT0();
        __syncthreads();               // data ready + prev compute finished
        if (c + 1 < total) {
            load_chunk(c + 1, buf ^ 1);  // overlaps with compute below
            CP_COMMIT();
        }

        const __nv_bfloat16* pA = &sA[buf][0];
        const __nv_bfloat16* pB = &sB[buf][0];
#pragma unroll
        for (int ks = 0; ks < 2; ks++) {
            const int kb = ks * 16 + t * 2;
            uint32_t af[4][4], bf[4][2];
#pragma unroll
            for (int mt = 0; mt < 4; mt++) {
                const int r = wm * 64 + mt * 16 + g;
                af[mt][0] = *(const uint32_t*)&pA[r * SSTR + kb];
                af[mt][1] = *(const uint32_t*)&pA[(r + 8) * SSTR + kb];
                af[mt][2] = *(const uint32_t*)&pA[r * SSTR + kb + 8];
                af[mt][3] = *(const uint32_t*)&pA[(r + 8) * SSTR + kb + 8];
            }
#pragma unroll
            for (int nt = 0; nt < 4; nt++) {
                const int cc = wn * 32 + nt * 8 + g;
                bf[nt][0] = *(const uint32_t*)&pB[cc * SSTR + kb];
                bf[nt][1] = *(const uint32_t*)&pB[cc * SSTR + kb + 8];
            }
#pragma unroll
            for (int mt = 0; mt < 4; mt++)
#pragma unroll
                for (int nt = 0; nt < 4; nt++)
                    mma16816(acc[mt][nt], af[mt][0], af[mt][1], af[mt][2],
                             af[mt][3], bf[nt][0], bf[nt][1]);
        }
        // ---- spill 2-step chain into exact fp32 accumulators -------------
#pragma unroll
        for (int mt = 0; mt < 4; mt++)
#pragma unroll
            for (int nt = 0; nt < 4; nt++)
#pragma unroll
                for (int q = 0; q < 4; q++) {
                    accP[mt][nt][q] += acc[mt][nt][q];
                    acc[mt][nt][q] = 0.f;
                }
    }

    // ---- epilogue --------------------------------------------------------
#pragma unroll
    for (int mt = 0; mt < 4; mt++) {
        const int r0 = m0 + wm * 64 + mt * 16 + g;
#pragma unroll
        for (int nt = 0; nt < 4; nt++) {
            const int cc = n0 + wn * 32 + nt * 8 + t * 2;
            if (cc >= Ntrue) continue;
            float v0 = accP[mt][nt][0], v1 = accP[mt][nt][1];
            float v2 = accP[mt][nt][2], v3 = accP[mt][nt][3];
            if (do_sp) {
                const float b0 = bias[cc], b1 = bias[cc + 1];
                v0 += b0; v1 += b1; v2 += b0; v3 += b1;
                v0 = fmaxf(v0, 0.f) + log1pf(expf(-fabsf(v0)));
                v1 = fmaxf(v1, 0.f) + log1pf(expf(-fabsf(v1)));
                v2 = fmaxf(v2, 0.f) + log1pf(expf(-fabsf(v2)));
                v3 = fmaxf(v3, 0.f) + log1pf(expf(-fabsf(v3)));
            }
            *(float2*)(C + (size_t)r0 * ldc + cc)       = make_float2(v0, v1);
            *(float2*)(C + (size_t)(r0 + 8) * ldc + cc) = make_float2(v2, v3);
        }
    }
}

// ---------------- depthwise causal conv (width 4) + bias + silu -----------
__global__ __launch_bounds__(256) void conv_silu_kernel(
    const float* __restrict__ xz, const float* __restrict__ cw,
    const float* __restrict__ cb, float* __restrict__ xs)
{
    const int i = blockIdx.x * blockDim.x + threadIdx.x;
    if (i >= ROWS * DI) return;
    const int d = i & (DI - 1);
    const int r = i >> 11;
    const int t = r & (LLEN - 1);
    float acc = cb[d];
    const float* base = xz + (size_t)r * XZW + d;
#pragma unroll
    for (int j = 0; j < DCONV; j++) {
        const int tt = t - (DCONV - 1) + j;
        if (tt >= 0)
            acc += cw[d * DCONV + j] * base[(long)(tt - t) * XZW];
    }
    xs[i] = acc / (1.f + __expf(-acc));
}

// ---------------- selective scan: 16 lanes per (b,d) channel --------------
__global__ __launch_bounds__(128) void scan_kernel(
    const float* __restrict__ xs, const float* __restrict__ delta,
    const float* __restrict__ xdbl, const float* __restrict__ A_log,
    const float* __restrict__ Dp, float* __restrict__ y)
{
    const int lane = threadIdx.x & 15;
    const int ch = blockIdx.x * (blockDim.x >> 4) + (threadIdx.x >> 4);
    const int b = ch / DI, d = ch & (DI - 1);
    const float A  = -expf(A_log[d * NSTATE + lane]);
    const float Dd = Dp[d];

    const float* xsP = xs    + (size_t)b * LLEN * DI + d;
    const float* dlP = delta + (size_t)b * LLEN * DI + d;
    const float* bcP = xdbl  + (size_t)b * LLEN * XDBLW + DTRANK + lane;
    float*       yP  = y     + (size_t)b * LLEN * DI + d;

    float h = 0.f;
    for (int t = 0; t < LLEN; t++) {
        const float dt = dlP[0];
        const float xt = xsP[0];
        const float Bt = bcP[0];
        const float Ct = bcP[NSTATE];
        const float dA = __expf(dt * A);
        h = dA * h + (dt * xt) * Bt;
        float p = h * Ct;
        p += __shfl_xor_sync(0xffffffffu, p, 1);
        p += __shfl_xor_sync(0xffffffffu, p, 2);
        p += __shfl_xor_sync(0xffffffffu, p, 4);
        p += __shfl_xor_sync(0xffffffffu, p, 8);
        if (lane == 0) yP[0] = p + Dd * xt;
        xsP += DI; dlP += DI; bcP += XDBLW; yP += DI;
    }
}

// ---------------- gate: y *= silu(z) --------------------------------------
__global__ __launch_bounds__(256) void gate_kernel(
    float* __restrict__ y, const float* __restrict__ xz)
{
    const int i = blockIdx.x * blockDim.x + threadIdx.x;
    if (i >= ROWS * DI) return;
    const int d = i & (DI - 1);
    const int r = i >> 11;
    const float z = xz[(size_t)r * XZW + DI + d];
    y[i] *= z / (1.f + __expf(-z));
}

// ---------------- rmsnorm per row -----------------------------------------
__global__ __launch_bounds__(256) void rmsnorm_kernel(
    const float* __restrict__ in, const float* __restrict__ w,
    float* __restrict__ out)
{
    const int r = blockIdx.x;
    const int tid = threadIdx.x;
    const float* row = in + (size_t)r * DDIM;
    float v[4];
    float ss = 0.f;
#pragma unroll
    for (int j = 0; j < 4; j++) {
        v[j] = row[tid + j * 256];
        ss += v[j] * v[j];
    }
#pragma unroll
    for (int o = 16; o > 0; o >>= 1) ss += __shfl_xor_sync(0xffffffffu, ss, o);
    __shared__ float ws[8];
    if ((tid & 31) == 0) ws[tid >> 5] = ss;
    __syncthreads();
    float tot = 0.f;
#pragma unroll
    for (int k = 0; k < 8; k++) tot += ws[k];
    const float inv = rsqrtf(tot * (1.f / (float)DDIM) + 1e-5f);
#pragma unroll
    for (int j = 0; j < 4; j++)
        out[(size_t)r * DDIM + tid + j * 256] = v[j] * inv * w[tid + j * 256];
}

// ---------------- host launch ---------------------------------------------
static inline int cdiv(long a, int b) { return (int)((a + b - 1) / b); }

extern "C" void kernel_launch(void* const* d_in, const int* in_sizes, int n_in,
                              void* d_out, int out_size)
{
    const float* x0   = (const float*)d_in[0];
    const float* Wi   = (const float*)d_in[1];   // [8, 4096, 1024]
    const float* cw   = (const float*)d_in[2];   // [8, 2048, 4]
    const float* cb   = (const float*)d_in[3];   // [8, 2048]
    const float* Wx   = (const float*)d_in[4];   // [8, 96, 2048]
    const float* Wdt  = (const float*)d_in[5];   // [8, 2048, 64]
    const float* bdt  = (const float*)d_in[6];   // [8, 2048]
    const float* Alog = (const float*)d_in[7];   // [8, 2048, 16]
    const float* Dp   = (const float*)d_in[8];   // [8, 2048]
    const float* Wo   = (const float*)d_in[9];   // [8, 1024, 2048]
    const float* rw   = (const float*)d_in[10];  // [8, 1024]

    float *xz, *xs, *xdbl, *delta, *y, *xb;
    __nv_bfloat16 *sa, *sw, *sdt;
    cudaGetSymbolAddress((void**)&xz,    g_xz);
    cudaGetSymbolAddress((void**)&xs,    g_xs);
    cudaGetSymbolAddress((void**)&xdbl,  g_xdbl);
    cudaGetSymbolAddress((void**)&delta, g_delta);
    cudaGetSymbolAddress((void**)&y,     g_y);
    cudaGetSymbolAddress((void**)&xb,    g_x);
    cudaGetSymbolAddress((void**)&sa,    g_sa);
    cudaGetSymbolAddress((void**)&sw,    g_sw);
    cudaGetSymbolAddress((void**)&sdt,   g_sdt);

    const float* xin = x0;
    for (int l = 0; l < DEPTH; l++) {
        // ---- in_proj: [4096,1024] x [4096,1024]^T -> xz [4096,4096] ------
        split2_kernel<<<cdiv((long)ROWS * DDIM, 256), 256>>>(
            xin, ROWS, ROWS, DDIM, DDIM, sa);
        split2_kernel<<<cdiv((long)XZW * DDIM, 256), 256>>>(
            Wi + (size_t)l * XZW * DDIM, XZW, XZW, DDIM, DDIM, sw);
        bf16_gemm_kernel<<<dim3(XZW / 128, ROWS / 128), 256>>>(
            sa, sw, xz, XZW, XZW, DDIM, 0, nullptr);

        // ---- depthwise causal conv + silu -> xs [4096,2048] --------------
        conv_silu_kernel<<<(ROWS * DI) / 256, 256>>>(
            xz, cw + (size_t)l * DI * DCONV, cb + (size_t)l * DI, xs);

        // ---- x_proj: [4096,2048] x [96,2048]^T -> xdbl [4096,96] ---------
        split2_kernel<<<cdiv((long)ROWS * DI, 256), 256>>>(
            xs, ROWS, ROWS, DI, DI, sa);
        split2_kernel<<<cdiv((long)128 * DI, 256), 256>>>(
            Wx + (size_t)l * XDBLW * DI, XDBLW, 128, DI, DI, sw);
        bf16_gemm_kernel<<<dim3(1, ROWS / 128), 256>>>(
            sa, sw, xdbl, XDBLW, XDBLW, DI, 0, nullptr);

        // ---- dt_proj + softplus: [4096,64] x [2048,64]^T -> delta --------
        split2_kernel<<<cdiv((long)ROWS * DTRANK, 256), 256>>>(
            xdbl, ROWS, ROWS, DTRANK, XDBLW, sdt);
        split2_kernel<<<cdiv((long)DI * DTRANK, 256), 256>>>(
            Wdt + (size_t)l * DI * DTRANK, DI, DI, DTRANK, DTRANK, sw);
        bf16_gemm_kernel<<<dim3(DI / 128, ROWS / 128), 256>>>(
            sdt, sw, delta, DI, DI, DTRANK, 1, bdt + (size_t)l * DI);

        // ---- selective scan (+ D skip) -----------------------------------
        scan_kernel<<<(BB * DI) / 8, 128>>>(
            xs, delta, xdbl, Alog + (size_t)l * DI * NSTATE, Dp + (size_t)l * DI, y);

        // ---- gate --------------------------------------------------------
        gate_kernel<<<(ROWS * DI) / 256, 256>>>(y, xz);

        // ---- out_proj: [4096,2048] x [1024,2048]^T -> xz [4096,1024] -----
        split2_kernel<<<cdiv((long)ROWS * DI, 256), 256>>>(
            y, ROWS, ROWS, DI, DI, sa);
        split2_kernel<<<cdiv((long)DDIM * DI, 256), 256>>>(
            Wo + (size_t)l * DDIM * DI, DDIM, DDIM, DI, DI, sw);
        bf16_gemm_kernel<<<dim3(DDIM / 128, ROWS / 128), 256>>>(
            sa, sw, xz, DDIM, DDIM, DI, 0, nullptr);

        // ---- rmsnorm -----------------------------------------------------
        float* outp = (l == DEPTH - 1) ? (float*)d_out : xb;
        rmsnorm_kernel<<<ROWS, 256>>>(xz, rw + (size_t)l * DDIM, outp);
        xin = xb;
    }
}